// round 1
// baseline (speedup 1.0000x reference)
#include <cuda_runtime.h>

#define NN 50000
#define NE 1600000

// ---------------- scratch (static device globals; no allocation) ----------------
__device__ int   g_cnt[NN];
__device__ int   g_cursor[NN];
__device__ int   g_base[NN];
__device__ int   g_bsum[64];
__device__ int   g_eid[NE];
__device__ float g_P[(size_t)NN * 32];
__device__ float g_msg[(size_t)NE * 32];          // 204.8 MB CSR-ordered messages
__device__ float g_mean[(size_t)NN * 32];
__device__ float g_std [(size_t)NN * 32];
__device__ float g_skew[(size_t)NN * 32];
__device__ float g_kurt[(size_t)NN * 32];
__device__ float g_outpre[(size_t)NN * 16];
__device__ float g_bnsum[16];
__device__ float g_bnsq[16];
__device__ float g_mu[16];
__device__ float g_rsig[16];

// ---------------- zero per-launch state ----------------
__global__ void k_zero() {
    int i = blockIdx.x * blockDim.x + threadIdx.x;
    if (i < NN) { g_cnt[i] = 0; g_cursor[i] = 0; }
    if (i < 16) { g_bnsum[i] = 0.f; g_bnsq[i] = 0.f; }
}

// ---------------- CSR build ----------------
__global__ void k_hist(const int* __restrict__ src) {
    int e = blockIdx.x * blockDim.x + threadIdx.x;
    if (e < NE) atomicAdd(&g_cnt[src[e]], 1);
}

__global__ void k_scan1() {
    __shared__ int sm[1024];
    int lt = threadIdx.x;
    int i = blockIdx.x * 1024 + lt;
    int v = (i < NN) ? g_cnt[i] : 0;
    sm[lt] = v;
    __syncthreads();
    #pragma unroll
    for (int off = 1; off < 1024; off <<= 1) {
        int x = (lt >= off) ? sm[lt - off] : 0;
        __syncthreads();
        sm[lt] += x;
        __syncthreads();
    }
    if (i < NN) g_base[i] = sm[lt] - v;        // exclusive
    if (lt == 1023) g_bsum[blockIdx.x] = sm[1023];
}

__global__ void k_scan2() {
    __shared__ int sm[64];
    int t = threadIdx.x;
    int nblk = (NN + 1023) / 1024;
    int v = (t < nblk) ? g_bsum[t] : 0;
    sm[t] = v;
    __syncthreads();
    #pragma unroll
    for (int off = 1; off < 64; off <<= 1) {
        int x = (t >= off) ? sm[t - off] : 0;
        __syncthreads();
        sm[t] += x;
        __syncthreads();
    }
    if (t < nblk) g_bsum[t] = sm[t] - v;       // exclusive
}

__global__ void k_scan3() {
    int i = blockIdx.x * 1024 + threadIdx.x;
    if (i < NN) g_base[i] += g_bsum[blockIdx.x];
}

__global__ void k_scatter(const int* __restrict__ src) {
    int e = blockIdx.x * blockDim.x + threadIdx.x;
    if (e < NE) {
        int s = src[e];
        int slot = g_base[s] + atomicAdd(&g_cursor[s], 1);
        g_eid[slot] = e;
    }
}

// ---------------- P = x_t @ W1a[0:16,:] + b1a ----------------
__global__ void k_pre(const float* __restrict__ x_t,
                      const float* __restrict__ W1a,
                      const float* __restrict__ b1a) {
    int n = blockIdx.x * blockDim.x + threadIdx.x;
    if (n >= NN) return;
    float x[16];
    const float4* xp = reinterpret_cast<const float4*>(x_t + (size_t)n * 16);
    #pragma unroll
    for (int q = 0; q < 4; q++) {
        float4 v = xp[q];
        x[4*q] = v.x; x[4*q+1] = v.y; x[4*q+2] = v.z; x[4*q+3] = v.w;
    }
    float p[32];
    #pragma unroll
    for (int j = 0; j < 32; j++) p[j] = __ldg(&b1a[j]);
    #pragma unroll
    for (int k = 0; k < 16; k++) {
        float a = x[k];
        #pragma unroll
        for (int j = 0; j < 32; j++) p[j] += a * __ldg(&W1a[k * 32 + j]);
    }
    float4* pp = reinterpret_cast<float4*>(g_P + (size_t)n * 32);
    #pragma unroll
    for (int q = 0; q < 8; q++) pp[q] = make_float4(p[4*q], p[4*q+1], p[4*q+2], p[4*q+3]);
}

// ---------------- edge MLP (CSR order) -> g_msg ----------------
__global__ __launch_bounds__(128) void k_edge(const float* __restrict__ edge_attr,
                                              const int*   __restrict__ tgt,
                                              const float* __restrict__ W1a,
                                              const float* __restrict__ W2a,
                                              const float* __restrict__ b2a) {
    __shared__ __align__(16) float sW1[16 * 32];
    __shared__ __align__(16) float sW2[32 * 32];
    __shared__ __align__(16) float sb2[32];
    for (int idx = threadIdx.x; idx < 512;  idx += 128) sW1[idx] = W1a[512 + idx];
    for (int idx = threadIdx.x; idx < 1024; idx += 128) sW2[idx] = W2a[idx];
    if (threadIdx.x < 32) sb2[threadIdx.x] = b2a[threadIdx.x];
    __syncthreads();

    int i = blockIdx.x * 128 + threadIdx.x;
    if (i >= NE) return;
    int e = g_eid[i];
    int t = tgt[e];

    float h[32];
    {
        const float4* Pp = reinterpret_cast<const float4*>(g_P + (size_t)t * 32);
        #pragma unroll
        for (int q = 0; q < 8; q++) {
            float4 p = Pp[q];
            h[4*q] = p.x; h[4*q+1] = p.y; h[4*q+2] = p.z; h[4*q+3] = p.w;
        }
    }
    float ea[16];
    {
        const float4* Ep = reinterpret_cast<const float4*>(edge_attr + (size_t)e * 16);
        #pragma unroll
        for (int q = 0; q < 4; q++) {
            float4 v = Ep[q];
            ea[4*q] = v.x; ea[4*q+1] = v.y; ea[4*q+2] = v.z; ea[4*q+3] = v.w;
        }
    }
    #pragma unroll
    for (int k = 0; k < 16; k++) {
        float a = ea[k];
        const float4* Wr = reinterpret_cast<const float4*>(sW1 + k * 32);
        #pragma unroll
        for (int q = 0; q < 8; q++) {
            float4 w = Wr[q];
            h[4*q]   += a * w.x; h[4*q+1] += a * w.y;
            h[4*q+2] += a * w.z; h[4*q+3] += a * w.w;
        }
    }
    #pragma unroll
    for (int j = 0; j < 32; j++) h[j] = (h[j] >= 0.f) ? h[j] : 0.1f * h[j];

    float m[32];
    #pragma unroll
    for (int j = 0; j < 32; j++) m[j] = sb2[j];
    #pragma unroll
    for (int k = 0; k < 32; k++) {
        float a = h[k];
        const float4* Wr = reinterpret_cast<const float4*>(sW2 + k * 32);
        #pragma unroll
        for (int q = 0; q < 8; q++) {
            float4 w = Wr[q];
            m[4*q]   += a * w.x; m[4*q+1] += a * w.y;
            m[4*q+2] += a * w.z; m[4*q+3] += a * w.w;
        }
    }
    float4* Mo = reinterpret_cast<float4*>(g_msg + (size_t)i * 32);
    #pragma unroll
    for (int q = 0; q < 8; q++) Mo[q] = make_float4(m[4*q], m[4*q+1], m[4*q+2], m[4*q+3]);
}

// ---------------- node-centric moments (warp per node, lane = feature) ----------------
__global__ void k_stats() {
    int gt = blockIdx.x * blockDim.x + threadIdx.x;
    int w = gt >> 5, lane = gt & 31;
    if (w >= NN) return;
    int beg = g_base[w];
    int c = g_cnt[w];
    float s1 = 0.f, s2 = 0.f;
    for (int i = 0; i < c; i++) {
        float m = g_msg[(size_t)(beg + i) * 32 + lane];
        s1 += m; s2 += m * m;
    }
    float denom = (c > 0) ? (float)c : 1.0f;
    float mean = s1 / denom;
    float var = s2 / denom - mean * mean;
    var = (var >= 0.f) ? var : 0.01f * var;
    float sd = sqrtf(var + 1e-6f);
    float rs = 1.0f / sd;
    float z3 = 0.f, z4 = 0.f;
    for (int i = 0; i < c; i++) {
        float m = g_msg[(size_t)(beg + i) * 32 + lane];
        float z = (m - mean) * rs;
        float z2 = z * z;
        z3 += z2 * z;
        z4 += z2 * z2;
    }
    size_t o = (size_t)w * 32 + lane;
    g_mean[o] = mean;
    g_std [o] = sd;
    g_skew[o] = z3 / denom;
    g_kurt[o] = z4 / denom;
}

// ---------------- node MLP (32-node tile, 4x5 register blocking) + BN partials ----------------
__global__ __launch_bounds__(256) void k_node_mlp(const float* __restrict__ x_s,
                                                  const float* __restrict__ u,
                                                  const float* __restrict__ W1b,
                                                  const float* __restrict__ b1b,
                                                  const float* __restrict__ W2b,
                                                  const float* __restrict__ b2b) {
    __shared__ float hc[32][160];
    __shared__ float h2s[32][164];
    __shared__ float sbn[16], sbnq[16];

    int base = blockIdx.x * 32;
    int tid = threadIdx.x;

    for (int idx = tid; idx < 32 * 160; idx += 256) {
        int nn = idx / 160, c = idx % 160;
        int v = base + nn;
        float val = 0.f;
        if (v < NN) {
            if      (c < 16)  val = x_s[(size_t)v * 16 + c];
            else if (c < 48)  val = g_mean[(size_t)v * 32 + (c - 16)];
            else if (c < 80)  val = g_std [(size_t)v * 32 + (c - 48)];
            else if (c < 112) val = g_skew[(size_t)v * 32 + (c - 80)];
            else if (c < 144) val = g_kurt[(size_t)v * 32 + (c - 112)];
            else              val = u[c - 144];
        }
        hc[nn][c] = val;
    }
    if (tid < 16) { sbn[tid] = 0.f; sbnq[tid] = 0.f; }
    __syncthreads();

    int tx = tid & 31, ty = tid >> 5;
    float acc[4][5];
    #pragma unroll
    for (int q = 0; q < 4; q++)
        #pragma unroll
        for (int r = 0; r < 5; r++) acc[q][r] = 0.f;

    #pragma unroll 4
    for (int k = 0; k < 160; k++) {
        float w[5];
        #pragma unroll
        for (int r = 0; r < 5; r++) w[r] = __ldg(&W1b[k * 160 + tx + 32 * r]);
        float a[4];
        #pragma unroll
        for (int q = 0; q < 4; q++) a[q] = hc[ty + 8 * q][k];
        #pragma unroll
        for (int q = 0; q < 4; q++)
            #pragma unroll
            for (int r = 0; r < 5; r++) acc[q][r] += a[q] * w[r];
    }
    #pragma unroll
    for (int q = 0; q < 4; q++)
        #pragma unroll
        for (int r = 0; r < 5; r++) {
            int j = tx + 32 * r;
            float hv = acc[q][r] + __ldg(&b1b[j]);
            hv = (hv >= 0.f) ? hv : 0.1f * hv;
            h2s[ty + 8 * q][j] = hv;
        }
    __syncthreads();

    int o = tid & 15, nr = tid >> 4;
    #pragma unroll
    for (int half = 0; half < 2; half++) {
        int nn = nr + 16 * half;
        float s = __ldg(&b2b[o]);
        #pragma unroll 8
        for (int k = 0; k < 160; k++) s += h2s[nn][k] * __ldg(&W2b[k * 16 + o]);
        int v = base + nn;
        if (v < NN) {
            g_outpre[(size_t)v * 16 + o] = s;
            atomicAdd(&sbn[o], s);
            atomicAdd(&sbnq[o], s * s);
        }
    }
    __syncthreads();
    if (tid < 16) {
        atomicAdd(&g_bnsum[tid], sbn[tid]);
        atomicAdd(&g_bnsq[tid], sbnq[tid]);
    }
}

// ---------------- BN finalize + apply ----------------
__global__ void k_bnfin() {
    int o = threadIdx.x;
    if (o < 16) {
        float mu = g_bnsum[o] / (float)NN;
        float var = g_bnsq[o] / (float)NN - mu * mu;
        g_mu[o] = mu;
        g_rsig[o] = rsqrtf(var + 1e-5f);
    }
}

__global__ void k_apply(const float* __restrict__ gamma,
                        const float* __restrict__ beta,
                        float* __restrict__ out) {
    int i = blockIdx.x * blockDim.x + threadIdx.x;
    if (i < NN * 16) {
        int o = i & 15;
        out[i] = gamma[o] * (g_outpre[i] - g_mu[o]) * g_rsig[o] + beta[o];
    }
}

// ---------------- launch ----------------
extern "C" void kernel_launch(void* const* d_in, const int* in_sizes, int n_in,
                              void* d_out, int out_size) {
    const float* x_s       = (const float*)d_in[0];
    const float* x_t       = (const float*)d_in[1];
    const float* edge_attr = (const float*)d_in[2];
    const float* u         = (const float*)d_in[3];
    const float* W1a       = (const float*)d_in[4];
    const float* b1a       = (const float*)d_in[5];
    const float* W2a       = (const float*)d_in[6];
    const float* b2a       = (const float*)d_in[7];
    const float* W1b       = (const float*)d_in[8];
    const float* b1b       = (const float*)d_in[9];
    const float* W2b       = (const float*)d_in[10];
    const float* b2b       = (const float*)d_in[11];
    const float* gamma     = (const float*)d_in[12];
    const float* beta      = (const float*)d_in[13];
    const int*   ei        = (const int*)d_in[14];
    const int* src = ei;
    const int* tgt = ei + NE;
    float* out = (float*)d_out;

    const int nScanBlk = (NN + 1023) / 1024;

    k_zero   <<<(NN + 255) / 256, 256>>>();
    k_hist   <<<(NE + 255) / 256, 256>>>(src);
    k_scan1  <<<nScanBlk, 1024>>>();
    k_scan2  <<<1, 64>>>();
    k_scan3  <<<nScanBlk, 1024>>>();
    k_scatter<<<(NE + 255) / 256, 256>>>(src);
    k_pre    <<<(NN + 255) / 256, 256>>>(x_t, W1a, b1a);
    k_edge   <<<NE / 128, 128>>>(edge_attr, tgt, W1a, W2a, b2a);
    k_stats  <<<(NN * 32 + 255) / 256, 256>>>();
    k_node_mlp<<<(NN + 31) / 32, 256>>>(x_s, u, W1b, b1b, W2b, b2b);
    k_bnfin  <<<1, 32>>>();
    k_apply  <<<(NN * 16 + 255) / 256, 256>>>(gamma, beta, out);
}

// round 2
// speedup vs baseline: 1.1017x; 1.1017x over previous
#include <cuda_runtime.h>

#define NN 50000
#define NE 1600000

// ---------------- scratch (static device globals; no allocation) ----------------
__device__ int   g_cnt[NN];
__device__ int   g_cursor[NN];
__device__ int   g_base[NN];
__device__ int   g_bsum[64];
__device__ int   g_eid[NE];
__device__ float g_P[(size_t)NN * 32];
__device__ float g_msg[(size_t)NE * 32];          // 204.8 MB CSR-ordered messages
__device__ float g_mean[(size_t)NN * 32];
__device__ float g_std [(size_t)NN * 32];
__device__ float g_skew[(size_t)NN * 32];
__device__ float g_kurt[(size_t)NN * 32];
__device__ float g_outpre[(size_t)NN * 16];
__device__ float g_bnsum[16];
__device__ float g_bnsq[16];
__device__ float g_mu[16];
__device__ float g_rsig[16];

// ---------------- init: zero state + P = x_t @ W1a[0:16,:] + b1a ----------------
__global__ void k_init(const float* __restrict__ x_t,
                       const float* __restrict__ W1a,
                       const float* __restrict__ b1a) {
    int n = blockIdx.x * blockDim.x + threadIdx.x;
    if (n < 16) { g_bnsum[n] = 0.f; g_bnsq[n] = 0.f; }
    if (n >= NN) return;
    g_cnt[n] = 0; g_cursor[n] = 0;

    float x[16];
    const float4* xp = reinterpret_cast<const float4*>(x_t + (size_t)n * 16);
    #pragma unroll
    for (int q = 0; q < 4; q++) {
        float4 v = xp[q];
        x[4*q] = v.x; x[4*q+1] = v.y; x[4*q+2] = v.z; x[4*q+3] = v.w;
    }
    float p[32];
    #pragma unroll
    for (int j = 0; j < 32; j++) p[j] = __ldg(&b1a[j]);
    #pragma unroll
    for (int k = 0; k < 16; k++) {
        float a = x[k];
        #pragma unroll
        for (int j = 0; j < 32; j++) p[j] += a * __ldg(&W1a[k * 32 + j]);
    }
    float4* pp = reinterpret_cast<float4*>(g_P + (size_t)n * 32);
    #pragma unroll
    for (int q = 0; q < 8; q++) pp[q] = make_float4(p[4*q], p[4*q+1], p[4*q+2], p[4*q+3]);
}

// ---------------- CSR build ----------------
__global__ void k_hist(const int* __restrict__ src) {
    int e = blockIdx.x * blockDim.x + threadIdx.x;
    if (e < NE) atomicAdd(&g_cnt[src[e]], 1);
}

__global__ void k_scan1() {
    __shared__ int sm[1024];
    int lt = threadIdx.x;
    int i = blockIdx.x * 1024 + lt;
    int v = (i < NN) ? g_cnt[i] : 0;
    sm[lt] = v;
    __syncthreads();
    #pragma unroll
    for (int off = 1; off < 1024; off <<= 1) {
        int x = (lt >= off) ? sm[lt - off] : 0;
        __syncthreads();
        sm[lt] += x;
        __syncthreads();
    }
    if (i < NN) g_base[i] = sm[lt] - v;        // exclusive within block
    if (lt == 1023) g_bsum[blockIdx.x] = sm[1023];
}

__global__ void k_scan2() {
    __shared__ int sm[64];
    int t = threadIdx.x;
    int nblk = (NN + 1023) / 1024;
    int v = (t < nblk) ? g_bsum[t] : 0;
    sm[t] = v;
    __syncthreads();
    #pragma unroll
    for (int off = 1; off < 64; off <<= 1) {
        int x = (t >= off) ? sm[t - off] : 0;
        __syncthreads();
        sm[t] += x;
        __syncthreads();
    }
    if (t < nblk) g_bsum[t] = sm[t] - v;       // exclusive block offsets
}

__global__ void k_scatter(const int* __restrict__ src) {
    int e = blockIdx.x * blockDim.x + threadIdx.x;
    if (e < NE) {
        int s = src[e];
        int slot = g_base[s] + g_bsum[s >> 10] + atomicAdd(&g_cursor[s], 1);
        g_eid[slot] = e;
    }
}

// ---------------- edge MLP (CSR order) -> g_msg (streaming stores) ----------------
__global__ __launch_bounds__(128) void k_edge(const float* __restrict__ edge_attr,
                                              const int*   __restrict__ tgt,
                                              const float* __restrict__ W1a,
                                              const float* __restrict__ W2a,
                                              const float* __restrict__ b2a) {
    __shared__ __align__(16) float sW1[16 * 32];
    __shared__ __align__(16) float sW2[32 * 32];
    __shared__ __align__(16) float sb2[32];
    for (int idx = threadIdx.x; idx < 512;  idx += 128) sW1[idx] = W1a[512 + idx];
    for (int idx = threadIdx.x; idx < 1024; idx += 128) sW2[idx] = W2a[idx];
    if (threadIdx.x < 32) sb2[threadIdx.x] = b2a[threadIdx.x];
    __syncthreads();

    int i = blockIdx.x * 128 + threadIdx.x;
    if (i >= NE) return;
    int e = g_eid[i];
    int t = tgt[e];

    float h[32];
    {
        const float4* Pp = reinterpret_cast<const float4*>(g_P + (size_t)t * 32);
        #pragma unroll
        for (int q = 0; q < 8; q++) {
            float4 p = Pp[q];
            h[4*q] = p.x; h[4*q+1] = p.y; h[4*q+2] = p.z; h[4*q+3] = p.w;
        }
    }
    // layer 1 (edge_attr part), consuming each float4 immediately
    {
        const float4* Ep = reinterpret_cast<const float4*>(edge_attr + (size_t)e * 16);
        #pragma unroll
        for (int q = 0; q < 4; q++) {
            float4 v = Ep[q];
            float a4[4] = {v.x, v.y, v.z, v.w};
            #pragma unroll
            for (int kk = 0; kk < 4; kk++) {
                float a = a4[kk];
                const float4* Wr = reinterpret_cast<const float4*>(sW1 + (4*q + kk) * 32);
                #pragma unroll
                for (int qq = 0; qq < 8; qq++) {
                    float4 w = Wr[qq];
                    h[4*qq]   += a * w.x; h[4*qq+1] += a * w.y;
                    h[4*qq+2] += a * w.z; h[4*qq+3] += a * w.w;
                }
            }
        }
    }
    #pragma unroll
    for (int j = 0; j < 32; j++) h[j] = (h[j] >= 0.f) ? h[j] : 0.1f * h[j];

    float m[32];
    #pragma unroll
    for (int j = 0; j < 32; j++) m[j] = sb2[j];
    #pragma unroll
    for (int k = 0; k < 32; k++) {
        float a = h[k];
        const float4* Wr = reinterpret_cast<const float4*>(sW2 + k * 32);
        #pragma unroll
        for (int q = 0; q < 8; q++) {
            float4 w = Wr[q];
            m[4*q]   += a * w.x; m[4*q+1] += a * w.y;
            m[4*q+2] += a * w.z; m[4*q+3] += a * w.w;
        }
    }
    float4* Mo = reinterpret_cast<float4*>(g_msg + (size_t)i * 32);
    #pragma unroll
    for (int q = 0; q < 8; q++)
        __stcs(Mo + q, make_float4(m[4*q], m[4*q+1], m[4*q+2], m[4*q+3]));
}

// ---------------- single-pass raw-moment stats (warp per node, lane = feature) ----------------
__global__ void k_stats() {
    int gt = blockIdx.x * blockDim.x + threadIdx.x;
    int w = gt >> 5, lane = gt & 31;
    if (w >= NN) return;
    int beg = g_base[w] + g_bsum[w >> 10];
    int c = g_cnt[w];
    const float* p = g_msg + (size_t)beg * 32 + lane;

    float s1 = 0.f, s2 = 0.f, s3 = 0.f, s4 = 0.f;
    int i = 0;
    for (; i + 4 <= c; i += 4) {
        float m0 = __ldcs(p + (size_t)(i + 0) * 32);
        float m1 = __ldcs(p + (size_t)(i + 1) * 32);
        float m2 = __ldcs(p + (size_t)(i + 2) * 32);
        float m3 = __ldcs(p + (size_t)(i + 3) * 32);
        float q0 = m0 * m0, q1 = m1 * m1, q2 = m2 * m2, q3 = m3 * m3;
        s1 += m0 + m1 + m2 + m3;
        s2 += q0 + q1 + q2 + q3;
        s3 += q0 * m0 + q1 * m1 + q2 * m2 + q3 * m3;
        s4 += q0 * q0 + q1 * q1 + q2 * q2 + q3 * q3;
    }
    for (; i < c; i++) {
        float m = __ldcs(p + (size_t)i * 32);
        float q = m * m;
        s1 += m; s2 += q; s3 += q * m; s4 += q * q;
    }

    float denom = (c > 0) ? (float)c : 1.0f;
    float mean = s1 / denom;
    float var = s2 / denom - mean * mean;
    var = (var >= 0.f) ? var : 0.01f * var;
    float sd = sqrtf(var + 1e-6f);
    float mean2 = mean * mean;
    // central moments from raw power sums
    float m3c = s3 - 3.f * mean * s2 + 3.f * mean2 * s1 - denom * mean2 * mean;
    float m4c = s4 - 4.f * mean * s3 + 6.f * mean2 * s2 - 4.f * mean2 * mean * s1
                + denom * mean2 * mean2;
    float inv_sd = 1.f / sd;
    float inv_sd2 = inv_sd * inv_sd;
    float skew = m3c * inv_sd2 * inv_sd / denom;
    float kurt = m4c * inv_sd2 * inv_sd2 / denom;

    size_t o = (size_t)w * 32 + lane;
    g_mean[o] = mean;
    g_std [o] = sd;
    g_skew[o] = skew;
    g_kurt[o] = kurt;
}

// ---------------- node MLP (32-node tile, 4x5 register blocking) + BN partials ----------------
__global__ __launch_bounds__(256) void k_node_mlp(const float* __restrict__ x_s,
                                                  const float* __restrict__ u,
                                                  const float* __restrict__ W1b,
                                                  const float* __restrict__ b1b,
                                                  const float* __restrict__ W2b,
                                                  const float* __restrict__ b2b) {
    __shared__ float hc[32][160];
    __shared__ float h2s[32][164];
    __shared__ float sbn[16], sbnq[16];

    int base = blockIdx.x * 32;
    int tid = threadIdx.x;

    for (int idx = tid; idx < 32 * 160; idx += 256) {
        int nn = idx / 160, c = idx % 160;
        int v = base + nn;
        float val = 0.f;
        if (v < NN) {
            if      (c < 16)  val = x_s[(size_t)v * 16 + c];
            else if (c < 48)  val = g_mean[(size_t)v * 32 + (c - 16)];
            else if (c < 80)  val = g_std [(size_t)v * 32 + (c - 48)];
            else if (c < 112) val = g_skew[(size_t)v * 32 + (c - 80)];
            else if (c < 144) val = g_kurt[(size_t)v * 32 + (c - 112)];
            else              val = u[c - 144];
        }
        hc[nn][c] = val;
    }
    if (tid < 16) { sbn[tid] = 0.f; sbnq[tid] = 0.f; }
    __syncthreads();

    int tx = tid & 31, ty = tid >> 5;
    float acc[4][5];
    #pragma unroll
    for (int q = 0; q < 4; q++)
        #pragma unroll
        for (int r = 0; r < 5; r++) acc[q][r] = 0.f;

    #pragma unroll 4
    for (int k = 0; k < 160; k++) {
        float w[5];
        #pragma unroll
        for (int r = 0; r < 5; r++) w[r] = __ldg(&W1b[k * 160 + tx + 32 * r]);
        float a[4];
        #pragma unroll
        for (int q = 0; q < 4; q++) a[q] = hc[ty + 8 * q][k];
        #pragma unroll
        for (int q = 0; q < 4; q++)
            #pragma unroll
            for (int r = 0; r < 5; r++) acc[q][r] += a[q] * w[r];
    }
    #pragma unroll
    for (int q = 0; q < 4; q++)
        #pragma unroll
        for (int r = 0; r < 5; r++) {
            int j = tx + 32 * r;
            float hv = acc[q][r] + __ldg(&b1b[j]);
            hv = (hv >= 0.f) ? hv : 0.1f * hv;
            h2s[ty + 8 * q][j] = hv;
        }
    __syncthreads();

    int o = tid & 15, nr = tid >> 4;
    #pragma unroll
    for (int half = 0; half < 2; half++) {
        int nn = nr + 16 * half;
        float s = __ldg(&b2b[o]);
        #pragma unroll 8
        for (int k = 0; k < 160; k++) s += h2s[nn][k] * __ldg(&W2b[k * 16 + o]);
        int v = base + nn;
        if (v < NN) {
            g_outpre[(size_t)v * 16 + o] = s;
            atomicAdd(&sbn[o], s);
            atomicAdd(&sbnq[o], s * s);
        }
    }
    __syncthreads();
    if (tid < 16) {
        atomicAdd(&g_bnsum[tid], sbn[tid]);
        atomicAdd(&g_bnsq[tid], sbnq[tid]);
    }
}

// ---------------- BN finalize + apply ----------------
__global__ void k_bnfin() {
    int o = threadIdx.x;
    if (o < 16) {
        float mu = g_bnsum[o] / (float)NN;
        float var = g_bnsq[o] / (float)NN - mu * mu;
        g_mu[o] = mu;
        g_rsig[o] = rsqrtf(var + 1e-5f);
    }
}

__global__ void k_apply(const float* __restrict__ gamma,
                        const float* __restrict__ beta,
                        float* __restrict__ out) {
    int i = blockIdx.x * blockDim.x + threadIdx.x;
    if (i < NN * 16) {
        int o = i & 15;
        out[i] = gamma[o] * (g_outpre[i] - g_mu[o]) * g_rsig[o] + beta[o];
    }
}

// ---------------- launch ----------------
extern "C" void kernel_launch(void* const* d_in, const int* in_sizes, int n_in,
                              void* d_out, int out_size) {
    const float* x_s       = (const float*)d_in[0];
    const float* x_t       = (const float*)d_in[1];
    const float* edge_attr = (const float*)d_in[2];
    const float* u         = (const float*)d_in[3];
    const float* W1a       = (const float*)d_in[4];
    const float* b1a       = (const float*)d_in[5];
    const float* W2a       = (const float*)d_in[6];
    const float* b2a       = (const float*)d_in[7];
    const float* W1b       = (const float*)d_in[8];
    const float* b1b       = (const float*)d_in[9];
    const float* W2b       = (const float*)d_in[10];
    const float* b2b       = (const float*)d_in[11];
    const float* gamma     = (const float*)d_in[12];
    const float* beta      = (const float*)d_in[13];
    const int*   ei        = (const int*)d_in[14];
    const int* src = ei;
    const int* tgt = ei + NE;
    float* out = (float*)d_out;

    const int nScanBlk = (NN + 1023) / 1024;

    k_init   <<<(NN + 255) / 256, 256>>>(x_t, W1a, b1a);   // #1
    k_hist   <<<(NE + 255) / 256, 256>>>(src);             // #2
    k_scan1  <<<nScanBlk, 1024>>>();                       // #3
    k_scan2  <<<1, 64>>>();                                // #4
    k_scatter<<<(NE + 255) / 256, 256>>>(src);             // #5
    k_edge   <<<NE / 128, 128>>>(edge_attr, tgt, W1a, W2a, b2a);  // #6 <- ncu -s 5 lands here
    k_stats  <<<(NN * 32 + 255) / 256, 256>>>();
    k_node_mlp<<<(NN + 31) / 32, 256>>>(x_s, u, W1b, b1b, W2b, b2b);
    k_bnfin  <<<1, 32>>>();
    k_apply  <<<(NN * 16 + 255) / 256, 256>>>(gamma, beta, out);
}

// round 3
// speedup vs baseline: 1.2543x; 1.1385x over previous
#include <cuda_runtime.h>

#define NN 50000
#define NE 1600000

// ---------------- scratch (static device globals; no allocation) ----------------
__device__ int   g_cnt[NN];
__device__ int   g_cursor[NN];
__device__ int   g_base[NN];
__device__ int   g_bsum[64];
__device__ int   g_eid[NE];
__device__ int   g_nid[NE];
__device__ float g_P[(size_t)NN * 32];
__device__ float g_s1[(size_t)NN * 32];
__device__ float g_s2[(size_t)NN * 32];
__device__ float g_s3[(size_t)NN * 32];
__device__ float g_s4[(size_t)NN * 32];
__device__ float g_outpre[(size_t)NN * 16];
__device__ float g_bnsum[16];
__device__ float g_bnsq[16];

// ---------------- init: zero state + P = x_t @ W1a[0:16,:] + b1a ----------------
__global__ void k_init(const float* __restrict__ x_t,
                       const float* __restrict__ W1a,
                       const float* __restrict__ b1a) {
    int i = blockIdx.x * blockDim.x + threadIdx.x;
    if (i < 16) { g_bnsum[i] = 0.f; g_bnsq[i] = 0.f; }
    if (i < NN * 32) {
        g_s1[i] = 0.f; g_s2[i] = 0.f; g_s3[i] = 0.f; g_s4[i] = 0.f;
    }
    if (i >= NN) return;
    g_cnt[i] = 0; g_cursor[i] = 0;

    float x[16];
    const float4* xp = reinterpret_cast<const float4*>(x_t + (size_t)i * 16);
    #pragma unroll
    for (int q = 0; q < 4; q++) {
        float4 v = xp[q];
        x[4*q] = v.x; x[4*q+1] = v.y; x[4*q+2] = v.z; x[4*q+3] = v.w;
    }
    float p[32];
    #pragma unroll
    for (int j = 0; j < 32; j++) p[j] = __ldg(&b1a[j]);
    #pragma unroll
    for (int k = 0; k < 16; k++) {
        float a = x[k];
        #pragma unroll
        for (int j = 0; j < 32; j++) p[j] += a * __ldg(&W1a[k * 32 + j]);
    }
    float4* pp = reinterpret_cast<float4*>(g_P + (size_t)i * 32);
    #pragma unroll
    for (int q = 0; q < 8; q++) pp[q] = make_float4(p[4*q], p[4*q+1], p[4*q+2], p[4*q+3]);
}

// ---------------- CSR build ----------------
__global__ void k_hist(const int* __restrict__ src) {
    int e = blockIdx.x * blockDim.x + threadIdx.x;
    if (e < NE) atomicAdd(&g_cnt[src[e]], 1);
}

__global__ void k_scan1() {
    __shared__ int sm[1024];
    int lt = threadIdx.x;
    int i = blockIdx.x * 1024 + lt;
    int v = (i < NN) ? g_cnt[i] : 0;
    sm[lt] = v;
    __syncthreads();
    #pragma unroll
    for (int off = 1; off < 1024; off <<= 1) {
        int x = (lt >= off) ? sm[lt - off] : 0;
        __syncthreads();
        sm[lt] += x;
        __syncthreads();
    }
    if (i < NN) g_base[i] = sm[lt] - v;        // exclusive within block
    if (lt == 1023) g_bsum[blockIdx.x] = sm[1023];
}

__global__ void k_scan2() {
    __shared__ int sm[64];
    int t = threadIdx.x;
    int nblk = (NN + 1023) / 1024;
    int v = (t < nblk) ? g_bsum[t] : 0;
    sm[t] = v;
    __syncthreads();
    #pragma unroll
    for (int off = 1; off < 64; off <<= 1) {
        int x = (t >= off) ? sm[t - off] : 0;
        __syncthreads();
        sm[t] += x;
        __syncthreads();
    }
    if (t < nblk) g_bsum[t] = sm[t] - v;       // exclusive block offsets
}

__global__ void k_scatter(const int* __restrict__ src) {
    int e = blockIdx.x * blockDim.x + threadIdx.x;
    if (e < NE) {
        int s = src[e];
        int slot = g_base[s] + g_bsum[s >> 10] + atomicAdd(&g_cursor[s], 1);
        g_eid[slot] = e;
        g_nid[slot] = s;
    }
}

// ---------------- fused edge MLP + moment accumulation (CSR order) ----------------
__global__ __launch_bounds__(128) void k_edge(const float* __restrict__ edge_attr,
                                              const int*   __restrict__ tgt,
                                              const float* __restrict__ W1a,
                                              const float* __restrict__ W2a,
                                              const float* __restrict__ b2a) {
    __shared__ __align__(16) float sW1[16 * 32];
    __shared__ __align__(16) float sW2[32 * 32];
    __shared__ __align__(16) float sb2[32];
    __shared__ float s_tile[128][33];
    __shared__ int   s_nid[128];
    for (int idx = threadIdx.x; idx < 512;  idx += 128) sW1[idx] = W1a[512 + idx];
    for (int idx = threadIdx.x; idx < 1024; idx += 128) sW2[idx] = W2a[idx];
    if (threadIdx.x < 32) sb2[threadIdx.x] = b2a[threadIdx.x];
    __syncthreads();

    int tid = threadIdx.x;
    int i = blockIdx.x * 128 + tid;       // NE % 128 == 0: always valid
    int e = g_eid[i];
    int t = tgt[e];
    s_nid[tid] = g_nid[i];

    float h[32];
    {
        const float4* Pp = reinterpret_cast<const float4*>(g_P + (size_t)t * 32);
        #pragma unroll
        for (int q = 0; q < 8; q++) {
            float4 p = Pp[q];
            h[4*q] = p.x; h[4*q+1] = p.y; h[4*q+2] = p.z; h[4*q+3] = p.w;
        }
    }
    {
        const float4* Ep = reinterpret_cast<const float4*>(edge_attr + (size_t)e * 16);
        #pragma unroll
        for (int q = 0; q < 4; q++) {
            float4 v = Ep[q];
            float a4[4] = {v.x, v.y, v.z, v.w};
            #pragma unroll
            for (int kk = 0; kk < 4; kk++) {
                float a = a4[kk];
                const float4* Wr = reinterpret_cast<const float4*>(sW1 + (4*q + kk) * 32);
                #pragma unroll
                for (int qq = 0; qq < 8; qq++) {
                    float4 w = Wr[qq];
                    h[4*qq]   += a * w.x; h[4*qq+1] += a * w.y;
                    h[4*qq+2] += a * w.z; h[4*qq+3] += a * w.w;
                }
            }
        }
    }
    #pragma unroll
    for (int j = 0; j < 32; j++) h[j] = (h[j] >= 0.f) ? h[j] : 0.1f * h[j];

    float m[32];
    #pragma unroll
    for (int j = 0; j < 32; j++) m[j] = sb2[j];
    #pragma unroll
    for (int k = 0; k < 32; k++) {
        float a = h[k];
        const float4* Wr = reinterpret_cast<const float4*>(sW2 + k * 32);
        #pragma unroll
        for (int q = 0; q < 8; q++) {
            float4 w = Wr[q];
            m[4*q]   += a * w.x; m[4*q+1] += a * w.y;
            m[4*q+2] += a * w.z; m[4*q+3] += a * w.w;
        }
    }
    // transpose into smem (row tid, padded stride 33 -> conflict-free)
    #pragma unroll
    for (int j = 0; j < 32; j++) s_tile[tid][j] = m[j];
    __syncthreads();

    // segmented moment reduction: thread (g, j) scans rows [32g, 32g+32), feature j
    int j = tid & 31, g = tid >> 5;
    int rbeg = g * 32;
    float s1 = 0.f, s2 = 0.f, s3 = 0.f, s4 = 0.f;
    int cur = s_nid[rbeg];
    #pragma unroll 4
    for (int r = rbeg; r < rbeg + 32; r++) {
        int nid = s_nid[r];
        if (nid != cur) {
            size_t o = (size_t)cur * 32 + j;
            atomicAdd(&g_s1[o], s1); atomicAdd(&g_s2[o], s2);
            atomicAdd(&g_s3[o], s3); atomicAdd(&g_s4[o], s4);
            s1 = s2 = s3 = s4 = 0.f;
            cur = nid;
        }
        float mv = s_tile[r][j];
        float qv = mv * mv;
        s1 += mv; s2 += qv; s3 += qv * mv; s4 += qv * qv;
    }
    {
        size_t o = (size_t)cur * 32 + j;
        atomicAdd(&g_s1[o], s1); atomicAdd(&g_s2[o], s2);
        atomicAdd(&g_s3[o], s3); atomicAdd(&g_s4[o], s4);
    }
}

// ---------------- node MLP (stats finalize inline) + BN partials ----------------
__global__ __launch_bounds__(256) void k_node_mlp(const float* __restrict__ x_s,
                                                  const float* __restrict__ u,
                                                  const float* __restrict__ W1b,
                                                  const float* __restrict__ b1b,
                                                  const float* __restrict__ W2b,
                                                  const float* __restrict__ b2b) {
    __shared__ float hc[32][160];
    __shared__ float h2s[32][164];
    __shared__ float sbn[16], sbnq[16];

    int base = blockIdx.x * 32;
    int tid = threadIdx.x;

    // stats finalize: (nn, feat) items
    for (int idx = tid; idx < 32 * 32; idx += 256) {
        int nn = idx >> 5, f = idx & 31;
        int v = base + nn;
        float mean = 0.f, sd = 0.f, skew = 0.f, kurt = 0.f;
        if (v < NN) {
            size_t o = (size_t)v * 32 + f;
            float s1 = g_s1[o], s2 = g_s2[o], s3 = g_s3[o], s4 = g_s4[o];
            int c = g_cnt[v];
            float denom = (c > 0) ? (float)c : 1.0f;
            mean = s1 / denom;
            float var = s2 / denom - mean * mean;
            var = (var >= 0.f) ? var : 0.01f * var;
            sd = sqrtf(var + 1e-6f);
            float mean2 = mean * mean;
            float m3c = s3 - 3.f * mean * s2 + 3.f * mean2 * s1 - denom * mean2 * mean;
            float m4c = s4 - 4.f * mean * s3 + 6.f * mean2 * s2
                        - 4.f * mean2 * mean * s1 + denom * mean2 * mean2;
            float inv_sd = 1.f / sd;
            float inv_sd2 = inv_sd * inv_sd;
            skew = m3c * inv_sd2 * inv_sd / denom;
            kurt = m4c * inv_sd2 * inv_sd2 / denom;
        }
        hc[nn][16 + f]  = mean;
        hc[nn][48 + f]  = sd;
        hc[nn][80 + f]  = skew;
        hc[nn][112 + f] = kurt;
    }
    // x_s and u
    for (int idx = tid; idx < 32 * 16; idx += 256) {
        int nn = idx >> 4, c = idx & 15;
        int v = base + nn;
        hc[nn][c] = (v < NN) ? x_s[(size_t)v * 16 + c] : 0.f;
        hc[nn][144 + c] = __ldg(&u[c]);
    }
    if (tid < 16) { sbn[tid] = 0.f; sbnq[tid] = 0.f; }
    __syncthreads();

    int tx = tid & 31, ty = tid >> 5;
    float acc[4][5];
    #pragma unroll
    for (int q = 0; q < 4; q++)
        #pragma unroll
        for (int r = 0; r < 5; r++) acc[q][r] = 0.f;

    #pragma unroll 4
    for (int k = 0; k < 160; k++) {
        float w[5];
        #pragma unroll
        for (int r = 0; r < 5; r++) w[r] = __ldg(&W1b[k * 160 + tx + 32 * r]);
        float a[4];
        #pragma unroll
        for (int q = 0; q < 4; q++) a[q] = hc[ty + 8 * q][k];
        #pragma unroll
        for (int q = 0; q < 4; q++)
            #pragma unroll
            for (int r = 0; r < 5; r++) acc[q][r] += a[q] * w[r];
    }
    #pragma unroll
    for (int q = 0; q < 4; q++)
        #pragma unroll
        for (int r = 0; r < 5; r++) {
            int jj = tx + 32 * r;
            float hv = acc[q][r] + __ldg(&b1b[jj]);
            hv = (hv >= 0.f) ? hv : 0.1f * hv;
            h2s[ty + 8 * q][jj] = hv;
        }
    __syncthreads();

    int o = tid & 15, nr = tid >> 4;
    #pragma unroll
    for (int half = 0; half < 2; half++) {
        int nn = nr + 16 * half;
        float s = __ldg(&b2b[o]);
        #pragma unroll 8
        for (int k = 0; k < 160; k++) s += h2s[nn][k] * __ldg(&W2b[k * 16 + o]);
        int v = base + nn;
        if (v < NN) {
            g_outpre[(size_t)v * 16 + o] = s;
            atomicAdd(&sbn[o], s);
            atomicAdd(&sbnq[o], s * s);
        }
    }
    __syncthreads();
    if (tid < 16) {
        atomicAdd(&g_bnsum[tid], sbn[tid]);
        atomicAdd(&g_bnsq[tid], sbnq[tid]);
    }
}

// ---------------- BN finalize folded into apply ----------------
__global__ void k_apply(const float* __restrict__ gamma,
                        const float* __restrict__ beta,
                        float* __restrict__ out) {
    int i = blockIdx.x * blockDim.x + threadIdx.x;
    if (i < NN * 16) {
        int o = i & 15;
        float mu = g_bnsum[o] * (1.0f / (float)NN);
        float var = g_bnsq[o] * (1.0f / (float)NN) - mu * mu;
        float rsig = rsqrtf(var + 1e-5f);
        out[i] = gamma[o] * (g_outpre[i] - mu) * rsig + beta[o];
    }
}

// ---------------- launch ----------------
extern "C" void kernel_launch(void* const* d_in, const int* in_sizes, int n_in,
                              void* d_out, int out_size) {
    const float* x_s       = (const float*)d_in[0];
    const float* x_t       = (const float*)d_in[1];
    const float* edge_attr = (const float*)d_in[2];
    const float* u         = (const float*)d_in[3];
    const float* W1a       = (const float*)d_in[4];
    const float* b1a       = (const float*)d_in[5];
    const float* W2a       = (const float*)d_in[6];
    const float* b2a       = (const float*)d_in[7];
    const float* W1b       = (const float*)d_in[8];
    const float* b1b       = (const float*)d_in[9];
    const float* W2b       = (const float*)d_in[10];
    const float* b2b       = (const float*)d_in[11];
    const float* gamma     = (const float*)d_in[12];
    const float* beta      = (const float*)d_in[13];
    const int*   ei        = (const int*)d_in[14];
    const int* src = ei;
    const int* tgt = ei + NE;
    float* out = (float*)d_out;

    const int nScanBlk = (NN + 1023) / 1024;

    k_init   <<<(NN * 32 + 255) / 256, 256>>>(x_t, W1a, b1a);
    k_hist   <<<(NE + 255) / 256, 256>>>(src);
    k_scan1  <<<nScanBlk, 1024>>>();
    k_scan2  <<<1, 64>>>();
    k_scatter<<<(NE + 255) / 256, 256>>>(src);
    k_edge   <<<NE / 128, 128>>>(edge_attr, tgt, W1a, W2a, b2a);
    k_node_mlp<<<(NN + 31) / 32, 256>>>(x_s, u, W1b, b1b, W2b, b2b);
    k_apply  <<<(NN * 16 + 255) / 256, 256>>>(gamma, beta, out);
}